// round 7
// baseline (speedup 1.0000x reference)
#include <cuda_runtime.h>
#include <cuda_bf16.h>

// AGNNConv:
//   Xp = X @ W;  attn[e] = dot(Xp[row[e]], Xp[col[e]]) * w
//   out[i] = sum_{e: row[e]==i} attn[e] * Xp[col[e]]
// Inputs: X [N*64 f32], W [64*64 f32], attention_w [1 f32],
//         row [E i32 sorted], col [E i32].  Output: out [N*64 f32]

#define D 64
#define MAX_NODES 50000
#define EPG 8               // edges per 8-lane group
#define EPW (4 * EPG)       // 32 edges per warp
#define RPB 128
#define XS_STRIDE 76

__device__ float4 g_Xp4[MAX_NODES * (D / 4)];

// ---------------------------------------------------------------------------
// Kernel 1: Xp = X @ W + zero out.  256 threads, 128 rows/block.
// ---------------------------------------------------------------------------
__global__ void __launch_bounds__(256)
gemm_zero_kernel(const float4* __restrict__ X4, const float4* __restrict__ W4,
                 float4* __restrict__ out4, int n_nodes)
{
    __shared__ float Ws[D * D];
    __shared__ float Xs[RPB * XS_STRIDE];

    int t  = threadIdx.x;
    int r0 = blockIdx.x * RPB;

    float4* Ws4v = reinterpret_cast<float4*>(Ws);
    #pragma unroll
    for (int i = 0; i < 4; ++i) Ws4v[t + 256 * i] = W4[t + 256 * i];

    #pragma unroll
    for (int i = 0; i < 8; ++i) {
        int idx4 = t + 256 * i;
        int r  = idx4 >> 4;
        int k4 = idx4 & 15;
        float4 v = (r0 + r < n_nodes) ? X4[(r0 + r) * 16 + k4]
                                      : make_float4(0.f, 0.f, 0.f, 0.f);
        *reinterpret_cast<float4*>(&Xs[r * XS_STRIDE + k4 * 4]) = v;
    }
    __syncthreads();

    int rg = t >> 3;
    int dg = t & 7;

    float acc[4][8];
    #pragma unroll
    for (int i = 0; i < 4; ++i)
        #pragma unroll
        for (int j = 0; j < 8; ++j) acc[i][j] = 0.f;

    const float* xbase = &Xs[(rg * 4) * XS_STRIDE];
    const float4* Wq = reinterpret_cast<const float4*>(Ws) + dg * 2;

    #pragma unroll 4
    for (int k4 = 0; k4 < 16; ++k4) {
        float4 xv[4];
        #pragma unroll
        for (int i = 0; i < 4; ++i)
            xv[i] = *reinterpret_cast<const float4*>(
                        &xbase[i * XS_STRIDE + k4 * 4]);

        #pragma unroll
        for (int kk = 0; kk < 4; ++kk) {
            int k = k4 * 4 + kk;
            float4 w0 = Wq[k * 16];
            float4 w1 = Wq[k * 16 + 1];
            #pragma unroll
            for (int i = 0; i < 4; ++i) {
                float x = reinterpret_cast<const float*>(&xv[i])[kk];
                acc[i][0] = fmaf(x, w0.x, acc[i][0]);
                acc[i][1] = fmaf(x, w0.y, acc[i][1]);
                acc[i][2] = fmaf(x, w0.z, acc[i][2]);
                acc[i][3] = fmaf(x, w0.w, acc[i][3]);
                acc[i][4] = fmaf(x, w1.x, acc[i][4]);
                acc[i][5] = fmaf(x, w1.y, acc[i][5]);
                acc[i][6] = fmaf(x, w1.z, acc[i][6]);
                acc[i][7] = fmaf(x, w1.w, acc[i][7]);
            }
        }
    }

    float4 z = make_float4(0.f, 0.f, 0.f, 0.f);
    #pragma unroll
    for (int i = 0; i < 4; ++i) {
        int r = r0 + rg * 4 + i;
        if (r < n_nodes) {
            int base = r * 16 + dg * 2;
            g_Xp4[base]     = make_float4(acc[i][0], acc[i][1], acc[i][2], acc[i][3]);
            g_Xp4[base + 1] = make_float4(acc[i][4], acc[i][5], acc[i][6], acc[i][7]);
            out4[base]      = z;
            out4[base + 1]  = z;
        }
    }
}

// ---------------------------------------------------------------------------
// Kernel 2: edge SDDMM + register SpMM scatter. R4 structure (no manual
// prefetch — occupancy is the latency hider), EPG=8 for 2x warp parallelism,
// int4-vectorized index loads (4 edges of row/col per LDG.128, broadcast
// within the 8-lane group) so the compiler can batch the xc loads itself.
// Lane q owns quads q and q+8: one 128B line per group-level load.
// ---------------------------------------------------------------------------
__global__ void __launch_bounds__(256)
edge_kernel(const int* __restrict__ row, const int* __restrict__ col,
            const float* __restrict__ attn_w, float4* __restrict__ out4,
            int n_edges)
{
    int warp_id = (blockIdx.x * blockDim.x + threadIdx.x) >> 5;
    int lane    = threadIdx.x & 31;
    int q       = lane & 7;

    int wbase = warp_id * EPW;
    if (wbase >= n_edges) return;

    int e0 = wbase + (lane >> 3) * EPG;
    const float w = __ldg(attn_w);

    if (wbase + EPW <= n_edges) {
        // ---- fast path: e0..e0+7 all valid, e0 % 8 == 0 -> int4 aligned ----
        const int4* row4 = reinterpret_cast<const int4*>(row + e0);
        const int4* col4 = reinterpret_cast<const int4*>(col + e0);

        int cur_r = -1;
        float4 xr0, xr1;
        float4 acc0 = make_float4(0.f, 0.f, 0.f, 0.f);
        float4 acc1 = make_float4(0.f, 0.f, 0.f, 0.f);
        bool first = true;

        #pragma unroll
        for (int j = 0; j < EPG / 4; ++j) {
            int4 rv = row4[j];
            int4 cv = col4[j];
            int rs[4] = {rv.x, rv.y, rv.z, rv.w};
            int cs[4] = {cv.x, cv.y, cv.z, cv.w};

            #pragma unroll
            for (int i = 0; i < 4; ++i) {
                int r = rs[i];
                int c = cs[i];

                if (r != cur_r) {
                    if (!first) {
                        atomicAdd(&out4[cur_r * 16 + q],     acc0);
                        atomicAdd(&out4[cur_r * 16 + 8 + q], acc1);
                        acc0 = make_float4(0.f, 0.f, 0.f, 0.f);
                        acc1 = make_float4(0.f, 0.f, 0.f, 0.f);
                    }
                    first = false;
                    cur_r = r;
                    xr0 = g_Xp4[r * 16 + q];
                    xr1 = g_Xp4[r * 16 + 8 + q];
                }

                float4 xc0 = g_Xp4[c * 16 + q];
                float4 xc1 = g_Xp4[c * 16 + 8 + q];

                float p = xc0.x * xr0.x + xc0.y * xr0.y + xc0.z * xr0.z + xc0.w * xr0.w
                        + xc1.x * xr1.x + xc1.y * xr1.y + xc1.z * xr1.z + xc1.w * xr1.w;
                p += __shfl_xor_sync(0xFFFFFFFFu, p, 4);
                p += __shfl_xor_sync(0xFFFFFFFFu, p, 2);
                p += __shfl_xor_sync(0xFFFFFFFFu, p, 1);

                float a = p * w;
                acc0.x = fmaf(a, xc0.x, acc0.x);
                acc0.y = fmaf(a, xc0.y, acc0.y);
                acc0.z = fmaf(a, xc0.z, acc0.z);
                acc0.w = fmaf(a, xc0.w, acc0.w);
                acc1.x = fmaf(a, xc1.x, acc1.x);
                acc1.y = fmaf(a, xc1.y, acc1.y);
                acc1.z = fmaf(a, xc1.z, acc1.z);
                acc1.w = fmaf(a, xc1.w, acc1.w);
            }
        }

        atomicAdd(&out4[cur_r * 16 + q],     acc0);
        atomicAdd(&out4[cur_r * 16 + 8 + q], acc1);
    } else {
        // ---- slow path: predicated, converged (unused for E%32==0) ----
        bool any  = e0 < n_edges;
        int e_end = any ? min(e0 + EPG, n_edges) : 0;
        int e_safe = any ? e0 : 0;

        int cur_r = row[e_safe];
        float4 xr0 = g_Xp4[cur_r * 16 + q];
        float4 xr1 = g_Xp4[cur_r * 16 + 8 + q];
        float4 acc0 = make_float4(0.f, 0.f, 0.f, 0.f);
        float4 acc1 = make_float4(0.f, 0.f, 0.f, 0.f);

        for (int i = 0; i < EPG; ++i) {
            int e = e0 + i;
            bool valid = any && (e < e_end);
            int ec = valid ? e : e_safe;

            int r = row[ec];
            int c = col[ec];

            if (valid && r != cur_r) {
                atomicAdd(&out4[cur_r * 16 + q],     acc0);
                atomicAdd(&out4[cur_r * 16 + 8 + q], acc1);
                acc0 = make_float4(0.f, 0.f, 0.f, 0.f);
                acc1 = make_float4(0.f, 0.f, 0.f, 0.f);
                cur_r = r;
                xr0 = g_Xp4[r * 16 + q];
                xr1 = g_Xp4[r * 16 + 8 + q];
            }

            float4 xc0 = g_Xp4[c * 16 + q];
            float4 xc1 = g_Xp4[c * 16 + 8 + q];
            float p = xc0.x * xr0.x + xc0.y * xr0.y + xc0.z * xr0.z + xc0.w * xr0.w
                    + xc1.x * xr1.x + xc1.y * xr1.y + xc1.z * xr1.z + xc1.w * xr1.w;
            p += __shfl_xor_sync(0xFFFFFFFFu, p, 4);
            p += __shfl_xor_sync(0xFFFFFFFFu, p, 2);
            p += __shfl_xor_sync(0xFFFFFFFFu, p, 1);

            if (valid) {
                float a = p * w;
                acc0.x = fmaf(a, xc0.x, acc0.x);
                acc0.y = fmaf(a, xc0.y, acc0.y);
                acc0.z = fmaf(a, xc0.z, acc0.z);
                acc0.w = fmaf(a, xc0.w, acc0.w);
                acc1.x = fmaf(a, xc1.x, acc1.x);
                acc1.y = fmaf(a, xc1.y, acc1.y);
                acc1.z = fmaf(a, xc1.z, acc1.z);
                acc1.w = fmaf(a, xc1.w, acc1.w);
            }
        }

        if (any) {
            atomicAdd(&out4[cur_r * 16 + q],     acc0);
            atomicAdd(&out4[cur_r * 16 + 8 + q], acc1);
        }
    }
}

// ---------------------------------------------------------------------------
extern "C" void kernel_launch(void* const* d_in, const int* in_sizes, int n_in,
                              void* d_out, int out_size)
{
    const float4* X4 = (const float4*)d_in[0];
    const float4* W4 = (const float4*)d_in[1];
    const float*  aw = (const float*)d_in[2];
    const int*   row = (const int*)d_in[3];
    const int*   col = (const int*)d_in[4];
    float4* out4 = (float4*)d_out;

    int n_nodes = in_sizes[0] / D;
    int n_edges = in_sizes[3];

    gemm_zero_kernel<<<(n_nodes + RPB - 1) / RPB, 256>>>(X4, W4, out4, n_nodes);

    int n_warps  = (n_edges + EPW - 1) / EPW;
    int n_blocks = (n_warps + 7) / 8;
    edge_kernel<<<n_blocks, 256>>>(row, col, aw, out4, n_edges);
}

// round 8
// speedup vs baseline: 1.0980x; 1.0980x over previous
#include <cuda_runtime.h>
#include <cuda_bf16.h>

// AGNNConv:
//   Xp = X @ W;  attn[e] = dot(Xp[row[e]], Xp[col[e]]) * w
//   out[i] = sum_{e: row[e]==i} attn[e] * Xp[col[e]]
// Inputs: X [N*64 f32], W [64*64 f32], attention_w [1 f32],
//         row [E i32 sorted], col [E i32].  Output: out [N*64 f32]

#define D 64
#define MAX_NODES 50000
#define EPG 16              // edges per 8-lane group (R4 config)
#define EPW (4 * EPG)       // 64 edges per warp
#define RPB 128
#define XS_STRIDE 76

__device__ float4 g_Xp4[MAX_NODES * (D / 4)];

// packed fp32x2 FMA: d = a*b + c elementwise on 2-wide fp32 pairs (sm_103a)
#define FFMA2(d, a, b, c) \
    asm("fma.rn.f32x2 %0, %1, %2, %3;" \
        : "=l"(d) : "l"(a), "l"(b), "l"(c))
#define PACK2(d, x) \
    asm("mov.b64 %0, {%1, %1};" : "=l"(d) : "r"(x))

union F4U2 { float4 f; unsigned long long u[2]; };

// ---------------------------------------------------------------------------
// Kernel 1: Xp = X @ W + zero out.  256 threads, 128 rows/block.
// Inner loop uses packed fma.rn.f32x2: 16 FFMA2 + 4 packs per k
// (vs 32 scalar FFMA) -> ~2x math throughput on the rt=2 FFMA pipe.
// ---------------------------------------------------------------------------
__global__ void __launch_bounds__(256)
gemm_zero_kernel(const float4* __restrict__ X4, const float4* __restrict__ W4,
                 float4* __restrict__ out4, int n_nodes)
{
    __shared__ float Ws[D * D];
    __shared__ float Xs[RPB * XS_STRIDE];

    int t  = threadIdx.x;
    int r0 = blockIdx.x * RPB;

    float4* Ws4v = reinterpret_cast<float4*>(Ws);
    #pragma unroll
    for (int i = 0; i < 4; ++i) Ws4v[t + 256 * i] = W4[t + 256 * i];

    #pragma unroll
    for (int i = 0; i < 8; ++i) {
        int idx4 = t + 256 * i;
        int r  = idx4 >> 4;
        int k4 = idx4 & 15;
        float4 v = (r0 + r < n_nodes) ? X4[(r0 + r) * 16 + k4]
                                      : make_float4(0.f, 0.f, 0.f, 0.f);
        *reinterpret_cast<float4*>(&Xs[r * XS_STRIDE + k4 * 4]) = v;
    }
    __syncthreads();

    int rg = t >> 3;
    int dg = t & 7;

    unsigned long long acc2[4][4];
    #pragma unroll
    for (int i = 0; i < 4; ++i)
        #pragma unroll
        for (int j = 0; j < 4; ++j) acc2[i][j] = 0ull;

    const float* xbase = &Xs[(rg * 4) * XS_STRIDE];
    const float4* Wq = reinterpret_cast<const float4*>(Ws) + dg * 2;

    #pragma unroll 4
    for (int k4 = 0; k4 < 16; ++k4) {
        float4 xv[4];
        #pragma unroll
        for (int i = 0; i < 4; ++i)
            xv[i] = *reinterpret_cast<const float4*>(
                        &xbase[i * XS_STRIDE + k4 * 4]);

        #pragma unroll
        for (int kk = 0; kk < 4; ++kk) {
            int k = k4 * 4 + kk;
            F4U2 w0, w1;
            w0.f = Wq[k * 16];
            w1.f = Wq[k * 16 + 1];
            #pragma unroll
            for (int i = 0; i < 4; ++i) {
                float x = reinterpret_cast<const float*>(&xv[i])[kk];
                unsigned long long xx;
                PACK2(xx, __float_as_uint(x));
                FFMA2(acc2[i][0], w0.u[0], xx, acc2[i][0]);
                FFMA2(acc2[i][1], w0.u[1], xx, acc2[i][1]);
                FFMA2(acc2[i][2], w1.u[0], xx, acc2[i][2]);
                FFMA2(acc2[i][3], w1.u[1], xx, acc2[i][3]);
            }
        }
    }

    float4 z = make_float4(0.f, 0.f, 0.f, 0.f);
    #pragma unroll
    for (int i = 0; i < 4; ++i) {
        int r = r0 + rg * 4 + i;
        if (r < n_nodes) {
            int base = r * 16 + dg * 2;
            F4U2 o0, o1;
            o0.u[0] = acc2[i][0]; o0.u[1] = acc2[i][1];
            o1.u[0] = acc2[i][2]; o1.u[1] = acc2[i][3];
            g_Xp4[base]     = o0.f;
            g_Xp4[base + 1] = o1.f;
            out4[base]      = z;
            out4[base + 1]  = z;
        }
    }
}

// ---------------------------------------------------------------------------
// Kernel 2: edge SDDMM + register SpMM scatter — exact R4 structure (best
// measured: 22.7us, 40 regs, occ 62%). Warp = 4 groups of 8 lanes; group
// handles EPG contiguous edges; lane q owns quads q and q+8 (one 128B line
// per group load). 3 shfl.xor serve all 4 groups. Sorted rows -> register
// accumulate, float4 atomic flush on segment change.
// ---------------------------------------------------------------------------
__global__ void __launch_bounds__(256)
edge_kernel(const int* __restrict__ row, const int* __restrict__ col,
            const float* __restrict__ attn_w, float4* __restrict__ out4,
            int n_edges)
{
    int warp_id = (blockIdx.x * blockDim.x + threadIdx.x) >> 5;
    int lane    = threadIdx.x & 31;
    int g       = lane >> 3;       // group 0..3
    int q       = lane & 7;        // quad owner

    int wbase = warp_id * EPW;
    if (wbase >= n_edges) return;

    int e0 = wbase + g * EPG;
    bool any = e0 < n_edges;
    int e_end = any ? min(e0 + EPG, n_edges) : e0;

    const float w = __ldg(attn_w);

    int cur_r = any ? row[e0] : 0;
    float4 xr0 = g_Xp4[cur_r * 16 + q];
    float4 xr1 = g_Xp4[cur_r * 16 + 8 + q];
    float4 acc0 = make_float4(0.f, 0.f, 0.f, 0.f);
    float4 acc1 = make_float4(0.f, 0.f, 0.f, 0.f);

    #pragma unroll 4
    for (int i = 0; i < EPG; ++i) {
        int e = e0 + i;
        bool valid = any && (e < e_end);
        int ec = valid ? e : (any ? e0 : 0);

        int r = row[ec];
        int c = col[ec];

        if (valid && r != cur_r) {
            atomicAdd(&out4[cur_r * 16 + q],     acc0);
            atomicAdd(&out4[cur_r * 16 + 8 + q], acc1);
            acc0 = make_float4(0.f, 0.f, 0.f, 0.f);
            acc1 = make_float4(0.f, 0.f, 0.f, 0.f);
            cur_r = r;
            xr0 = g_Xp4[r * 16 + q];
            xr1 = g_Xp4[r * 16 + 8 + q];
        }

        float4 xc0 = g_Xp4[c * 16 + q];
        float4 xc1 = g_Xp4[c * 16 + 8 + q];

        float p = xc0.x * xr0.x + xc0.y * xr0.y + xc0.z * xr0.z + xc0.w * xr0.w
                + xc1.x * xr1.x + xc1.y * xr1.y + xc1.z * xr1.z + xc1.w * xr1.w;

        p += __shfl_xor_sync(0xFFFFFFFFu, p, 4);
        p += __shfl_xor_sync(0xFFFFFFFFu, p, 2);
        p += __shfl_xor_sync(0xFFFFFFFFu, p, 1);

        if (valid) {
            float a = p * w;
            acc0.x = fmaf(a, xc0.x, acc0.x);
            acc0.y = fmaf(a, xc0.y, acc0.y);
            acc0.z = fmaf(a, xc0.z, acc0.z);
            acc0.w = fmaf(a, xc0.w, acc0.w);
            acc1.x = fmaf(a, xc1.x, acc1.x);
            acc1.y = fmaf(a, xc1.y, acc1.y);
            acc1.z = fmaf(a, xc1.z, acc1.z);
            acc1.w = fmaf(a, xc1.w, acc1.w);
        }
    }

    if (any) {
        atomicAdd(&out4[cur_r * 16 + q],     acc0);
        atomicAdd(&out4[cur_r * 16 + 8 + q], acc1);
    }
}

// ---------------------------------------------------------------------------
extern "C" void kernel_launch(void* const* d_in, const int* in_sizes, int n_in,
                              void* d_out, int out_size)
{
    const float4* X4 = (const float4*)d_in[0];
    const float4* W4 = (const float4*)d_in[1];
    const float*  aw = (const float*)d_in[2];
    const int*   row = (const int*)d_in[3];
    const int*   col = (const int*)d_in[4];
    float4* out4 = (float4*)d_out;

    int n_nodes = in_sizes[0] / D;
    int n_edges = in_sizes[3];

    gemm_zero_kernel<<<(n_nodes + RPB - 1) / RPB, 256>>>(X4, W4, out4, n_nodes);

    int n_warps  = (n_edges + EPW - 1) / EPW;
    int n_blocks = (n_warps + 7) / 8;   // 8 warps per 256-thread block
    edge_kernel<<<n_blocks, 256>>>(row, col, aw, out4, n_edges);
}

// round 9
// speedup vs baseline: 1.3829x; 1.2595x over previous
#include <cuda_runtime.h>
#include <cuda_bf16.h>
#include <cstdint>

// AGNNConv:
//   Xp = X @ W;  attn[e] = dot(Xp[row[e]], Xp[col[e]]) * w
//   out[i] = sum_{e: row[e]==i} attn[e] * Xp[col[e]]
// Inputs: X [N*64 f32], W [64*64 f32], attention_w [1 f32],
//         row [E i32 sorted], col [E i32].  Output: out [N*64 f32]

#define D 64
#define MAX_NODES 50000
#define EPG 16              // edges per 8-lane group (validated R4 config)
#define EPW (4 * EPG)       // 64 edges per warp
#define RPB 128             // rows per block (gemm)
#define XS_STRIDE 68        // fp32 row stride in smem (8B-aligned frag loads)
#define BPK 34              // Bh/Bl row stride (k2 dimension padded 32->34)

__device__ float4 g_Xp4[MAX_NODES * (D / 4)];

// ---------------------------------------------------------------------------
// helpers: bf16 split + pack
// ---------------------------------------------------------------------------
__device__ __forceinline__ uint32_t pack_bf16(float x, float y) {
    __nv_bfloat162 p = __floats2bfloat162_rn(x, y);   // .x = low half
    return *reinterpret_cast<uint32_t*>(&p);
}
__device__ __forceinline__ void split_bf16(float x, float& h, float& l) {
    __nv_bfloat16 bh = __float2bfloat16_rn(x);
    h = __bfloat162float(bh);
    l = x - h;                                        // exact in fp32
}

__device__ __forceinline__ void mma16816(float* d, const uint32_t* a,
                                         uint32_t b0, uint32_t b1) {
    asm volatile(
        "mma.sync.aligned.m16n8k16.row.col.f32.bf16.bf16.f32 "
        "{%0,%1,%2,%3}, {%4,%5,%6,%7}, {%8,%9}, {%0,%1,%2,%3};"
        : "+f"(d[0]), "+f"(d[1]), "+f"(d[2]), "+f"(d[3])
        : "r"(a[0]), "r"(a[1]), "r"(a[2]), "r"(a[3]), "r"(b0), "r"(b1));
}

// ---------------------------------------------------------------------------
// Kernel 1: Xp = X @ W + zero out, via tensor cores (bf16 3-term split).
// 256 threads = 8 warps; block computes 128 rows; warp w -> rows [16w,16w+16).
// Per warp: 4 k-steps x 8 n-tiles x 3 HMMA (hh, hl, lh) = 96 mma.
// A frags converted on the fly from fp32 smem; W pre-split/packed in smem.
// ---------------------------------------------------------------------------
__global__ void __launch_bounds__(256)
gemm_zero_kernel(const float4* __restrict__ X4, const float* __restrict__ W,
                 float2* __restrict__ out2, int n_nodes)
{
    __shared__ float    Xs[RPB * XS_STRIDE];   // 34.8 KB fp32 tile
    __shared__ uint32_t Bh[D * BPK];           // 8.7 KB  [n][k2] hi pairs
    __shared__ uint32_t Bl[D * BPK];           // 8.7 KB  [n][k2] lo pairs

    int t  = threadIdx.x;
    int r0 = blockIdx.x * RPB;

    // ---- convert W into packed bf16 hi/lo pairs: Bh[n][k2] = {W[2k2][n], W[2k2+1][n]}
    #pragma unroll
    for (int i = 0; i < 8; ++i) {
        int idx = t + 256 * i;                 // 2048 (k2,n) pairs
        int k2 = idx >> 6;
        int n  = idx & 63;
        float w0 = W[(2 * k2) * D + n];
        float w1 = W[(2 * k2 + 1) * D + n];
        float h0, l0, h1, l1;
        split_bf16(w0, h0, l0);
        split_bf16(w1, h1, l1);
        Bh[n * BPK + k2] = pack_bf16(h0, h1);
        Bl[n * BPK + k2] = pack_bf16(l0, l1);
    }

    // ---- load X tile (fp32) into smem
    #pragma unroll
    for (int i = 0; i < 8; ++i) {
        int idx4 = t + 256 * i;                // 2048 float4
        int r  = idx4 >> 4;
        int k4 = idx4 & 15;
        float4 v = (r0 + r < n_nodes) ? X4[(r0 + r) * 16 + k4]
                                      : make_float4(0.f, 0.f, 0.f, 0.f);
        *reinterpret_cast<float4*>(&Xs[r * XS_STRIDE + k4 * 4]) = v;
    }
    __syncthreads();

    int warp = t >> 5;
    int lane = t & 31;
    int g  = lane >> 2;                        // 0..7
    int tq = lane & 3;                         // 0..3
    int wbase = warp * 16;

    float acc[8][4];
    #pragma unroll
    for (int j = 0; j < 8; ++j)
        #pragma unroll
        for (int k = 0; k < 4; ++k) acc[j][k] = 0.f;

    const float* row0 = &Xs[(wbase + g) * XS_STRIDE];
    const float* row1 = &Xs[(wbase + g + 8) * XS_STRIDE];

    #pragma unroll
    for (int s = 0; s < 4; ++s) {
        // A fragments: a0=(g,2t),(g,2t+1)  a1=(g+8,...)  a2=(g,2t+8..)  a3=(g+8,2t+8..)
        float2 v00 = *reinterpret_cast<const float2*>(&row0[16 * s + 2 * tq]);
        float2 v10 = *reinterpret_cast<const float2*>(&row1[16 * s + 2 * tq]);
        float2 v01 = *reinterpret_cast<const float2*>(&row0[16 * s + 2 * tq + 8]);
        float2 v11 = *reinterpret_cast<const float2*>(&row1[16 * s + 2 * tq + 8]);

        float h, l, h2, l2;
        uint32_t Ah[4], Al[4];
        split_bf16(v00.x, h, l); split_bf16(v00.y, h2, l2);
        Ah[0] = pack_bf16(h, h2);  Al[0] = pack_bf16(l, l2);
        split_bf16(v10.x, h, l); split_bf16(v10.y, h2, l2);
        Ah[1] = pack_bf16(h, h2);  Al[1] = pack_bf16(l, l2);
        split_bf16(v01.x, h, l); split_bf16(v01.y, h2, l2);
        Ah[2] = pack_bf16(h, h2);  Al[2] = pack_bf16(l, l2);
        split_bf16(v11.x, h, l); split_bf16(v11.y, h2, l2);
        Ah[3] = pack_bf16(h, h2);  Al[3] = pack_bf16(l, l2);

        #pragma unroll
        for (int j = 0; j < 8; ++j) {
            int nrow = (8 * j + g) * BPK + 8 * s + tq;
            uint32_t b0h = Bh[nrow];
            uint32_t b1h = Bh[nrow + 4];
            uint32_t b0l = Bl[nrow];
            uint32_t b1l = Bl[nrow + 4];
            mma16816(acc[j], Ah, b0h, b1h);    // hi*hi
            mma16816(acc[j], Ah, b0l, b1l);    // hi*lo
            mma16816(acc[j], Al, b0h, b1h);    // lo*hi
        }
    }

    // ---- epilogue: D tile (g,2t),(g,2t+1),(g+8,2t),(g+8,2t+1) per n-tile j
    float2* Xp2 = reinterpret_cast<float2*>(g_Xp4);
    float2 z2 = make_float2(0.f, 0.f);
    int ra = r0 + wbase + g;
    int rb = ra + 8;
    #pragma unroll
    for (int j = 0; j < 8; ++j) {
        int cpair = (8 * j + 2 * tq) >> 1;     // float2 column index (0..31)
        if (ra < n_nodes) {
            Xp2[ra * 32 + cpair]  = make_float2(acc[j][0], acc[j][1]);
            out2[ra * 32 + cpair] = z2;
        }
        if (rb < n_nodes) {
            Xp2[rb * 32 + cpair]  = make_float2(acc[j][2], acc[j][3]);
            out2[rb * 32 + cpair] = z2;
        }
    }
}

// ---------------------------------------------------------------------------
// Kernel 2: edge SDDMM + register SpMM scatter — exact R4/R8 structure
// (best measured: 22.9us, 40 regs, occ 62%). Warp = 4 groups of 8 lanes;
// group handles EPG contiguous edges; lane q owns quads q and q+8.
// 3 shfl.xor serve all 4 groups. Sorted rows -> register accumulate,
// float4 atomic flush on segment change.
// ---------------------------------------------------------------------------
__global__ void __launch_bounds__(256)
edge_kernel(const int* __restrict__ row, const int* __restrict__ col,
            const float* __restrict__ attn_w, float4* __restrict__ out4,
            int n_edges)
{
    int warp_id = (blockIdx.x * blockDim.x + threadIdx.x) >> 5;
    int lane    = threadIdx.x & 31;
    int g       = lane >> 3;
    int q       = lane & 7;

    int wbase = warp_id * EPW;
    if (wbase >= n_edges) return;

    int e0 = wbase + g * EPG;
    bool any = e0 < n_edges;
    int e_end = any ? min(e0 + EPG, n_edges) : e0;

    const float w = __ldg(attn_w);

    int cur_r = any ? row[e0] : 0;
    float4 xr0 = g_Xp4[cur_r * 16 + q];
    float4 xr1 = g_Xp4[cur_r * 16 + 8 + q];
    float4 acc0 = make_float4(0.f, 0.f, 0.f, 0.f);
    float4 acc1 = make_float4(0.f, 0.f, 0.f, 0.f);

    #pragma unroll 4
    for (int i = 0; i < EPG; ++i) {
        int e = e0 + i;
        bool valid = any && (e < e_end);
        int ec = valid ? e : (any ? e0 : 0);

        int r = row[ec];
        int c = col[ec];

        if (valid && r != cur_r) {
            atomicAdd(&out4[cur_r * 16 + q],     acc0);
            atomicAdd(&out4[cur_r * 16 + 8 + q], acc1);
            acc0 = make_float4(0.f, 0.f, 0.f, 0.f);
            acc1 = make_float4(0.f, 0.f, 0.f, 0.f);
            cur_r = r;
            xr0 = g_Xp4[r * 16 + q];
            xr1 = g_Xp4[r * 16 + 8 + q];
        }

        float4 xc0 = g_Xp4[c * 16 + q];
        float4 xc1 = g_Xp4[c * 16 + 8 + q];

        float p = xc0.x * xr0.x + xc0.y * xr0.y + xc0.z * xr0.z + xc0.w * xr0.w
                + xc1.x * xr1.x + xc1.y * xr1.y + xc1.z * xr1.z + xc1.w * xr1.w;

        p += __shfl_xor_sync(0xFFFFFFFFu, p, 4);
        p += __shfl_xor_sync(0xFFFFFFFFu, p, 2);
        p += __shfl_xor_sync(0xFFFFFFFFu, p, 1);

        if (valid) {
            float a = p * w;
            acc0.x = fmaf(a, xc0.x, acc0.x);
            acc0.y = fmaf(a, xc0.y, acc0.y);
            acc0.z = fmaf(a, xc0.z, acc0.z);
            acc0.w = fmaf(a, xc0.w, acc0.w);
            acc1.x = fmaf(a, xc1.x, acc1.x);
            acc1.y = fmaf(a, xc1.y, acc1.y);
            acc1.z = fmaf(a, xc1.z, acc1.z);
            acc1.w = fmaf(a, xc1.w, acc1.w);
        }
    }

    if (any) {
        atomicAdd(&out4[cur_r * 16 + q],     acc0);
        atomicAdd(&out4[cur_r * 16 + 8 + q], acc1);
    }
}

// ---------------------------------------------------------------------------
extern "C" void kernel_launch(void* const* d_in, const int* in_sizes, int n_in,
                              void* d_out, int out_size)
{
    const float4* X4 = (const float4*)d_in[0];
    const float*  W  = (const float*)d_in[1];
    const float*  aw = (const float*)d_in[2];
    const int*   row = (const int*)d_in[3];
    const int*   col = (const int*)d_in[4];

    int n_nodes = in_sizes[0] / D;
    int n_edges = in_sizes[3];

    gemm_zero_kernel<<<(n_nodes + RPB - 1) / RPB, 256>>>(
        X4, W, (float2*)d_out, n_nodes);

    int n_warps  = (n_edges + EPW - 1) / EPW;
    int n_blocks = (n_warps + 7) / 8;
    edge_kernel<<<n_blocks, 256>>>(row, col, aw, (float4*)d_out, n_edges);
}